// round 14
// baseline (speedup 1.0000x reference)
#include <cuda_runtime.h>
#include <cuda_bf16.h>
#include <cuda_fp16.h>
#include <math.h>
#include <stdint.h>

#define BB    512
#define OO    16
#define OBS   128
#define HH    512
#define NNODE (BB*OO)
#define LN_EPS 1e-5f

// ---------------- scratch ----------------
__device__ __align__(16) float g_PQ[(size_t)NNODE * 1024];
__device__ __align__(16) float g_S [(size_t)NNODE * HH];
__device__ __align__(16) float g_T [(size_t)NNODE * HH];
__device__ __align__(16) float g_H1[(size_t)NNODE * HH];   // Wcomb fp32 temp
__device__ __align__(16) float g_bp[512];

// fragment-packed weights
__device__ __align__(16) uint4 g_eW1aH[8192],  g_eW1aL[8192];    // fp16
__device__ __align__(16) uint4 g_eW1bH[8192],  g_eW1bL[8192];    // fp16
__device__ __align__(16) uint4 g_W2H[32768],   g_W2L[32768];     // fp16 (edge; lo unused)
__device__ __align__(16) uint4 g_nW1aH[8192],  g_nW1aL[8192];    // fp16
__device__ __align__(16) uint4 g_nW1cH[32768], g_nW1cL[32768];   // bf16 (for wc)
__device__ __align__(16) uint4 g_nW2H[32768],  g_nW2L[32768];    // fp16
__device__ __align__(16) uint4 g_nW3H[8192],   g_nW3L[8192];     // fp16
__device__ __align__(16) uint4 g_WcH[32768],   g_WcL[32768];     // fp16

// ---------------- helpers ----------------
__device__ __forceinline__ uint32_t smem_u32(const void* p) {
    uint32_t a;
    asm("{ .reg .u64 t; cvta.to.shared.u64 t, %1; cvt.u32.u64 %0, t; }" : "=r"(a) : "l"(p));
    return a;
}
__device__ __forceinline__ void ldsm4(uint32_t* r, uint32_t addr) {
    asm volatile("ldmatrix.sync.aligned.m8n8.x4.shared.b16 {%0,%1,%2,%3}, [%4];"
        : "=r"(r[0]), "=r"(r[1]), "=r"(r[2]), "=r"(r[3]) : "r"(addr));
}
__device__ __forceinline__ uint4 lds128(uint32_t a) {
    uint4 v;
    asm volatile("ld.shared.v4.b32 {%0,%1,%2,%3}, [%4];"
        : "=r"(v.x), "=r"(v.y), "=r"(v.z), "=r"(v.w) : "r"(a));
    return v;
}
__device__ __forceinline__ void mma_bf16(float* c, const uint32_t* a, uint32_t b0, uint32_t b1) {
    asm volatile(
        "mma.sync.aligned.m16n8k16.row.col.f32.bf16.bf16.f32 "
        "{%0,%1,%2,%3}, {%4,%5,%6,%7}, {%8,%9}, {%0,%1,%2,%3};"
        : "+f"(c[0]), "+f"(c[1]), "+f"(c[2]), "+f"(c[3])
        : "r"(a[0]), "r"(a[1]), "r"(a[2]), "r"(a[3]), "r"(b0), "r"(b1));
}
__device__ __forceinline__ void mma_f16(float* c, const uint32_t* a, uint32_t b0, uint32_t b1) {
    asm volatile(
        "mma.sync.aligned.m16n8k16.row.col.f32.f16.f16.f32 "
        "{%0,%1,%2,%3}, {%4,%5,%6,%7}, {%8,%9}, {%0,%1,%2,%3};"
        : "+f"(c[0]), "+f"(c[1]), "+f"(c[2]), "+f"(c[3])
        : "r"(a[0]), "r"(a[1]), "r"(a[2]), "r"(a[3]), "r"(b0), "r"(b1));
}
#define CP_ASYNC16(dst, src) \
    asm volatile("cp.async.cg.shared.global [%0], [%1], 16;" \
                 :: "r"(dst), "l"(__cvta_generic_to_global(src)))
#define CP_COMMIT() asm volatile("cp.async.commit_group;" ::: "memory")
#define CP_WAIT0()  asm volatile("cp.async.wait_group 0;" ::: "memory")
#define CP_WAIT1()  asm volatile("cp.async.wait_group 1;" ::: "memory")
#define CP_WAIT2()  asm volatile("cp.async.wait_group 2;" ::: "memory")
#define CP_WAIT3()  asm volatile("cp.async.wait_group 3;" ::: "memory")

__device__ __forceinline__ uint32_t pack_bf_pair(float a, float b, float& ra, float& rb) {
    const __nv_bfloat16 ha = __float2bfloat16(a), hb = __float2bfloat16(b);
    ra = a - __bfloat162float(ha);
    rb = b - __bfloat162float(hb);
    return (uint32_t)__bfloat16_as_ushort(ha) | ((uint32_t)__bfloat16_as_ushort(hb) << 16);
}
__device__ __forceinline__ uint32_t pack_h_pair(float a, float b, float& ra, float& rb) {
    const __half ha = __float2half_rn(a), hb = __float2half_rn(b);
    ra = a - __half2float(ha);
    rb = b - __half2float(hb);
    return (uint32_t)__half_as_ushort(ha) | ((uint32_t)__half_as_ushort(hb) << 16);
}

// ---------------- pack one fragment item ----------------
__device__ __forceinline__ void pack_item(
    const float* __restrict__ W, int ldW, int npairs,
    uint4* __restrict__ dH, uint4* __restrict__ dL, bool f16, int item)
{
    const int lane = item & 31;
    const int gid = lane >> 2, tg = lane & 3;
    const int jp = (item >> 5) % npairs;
    const int s = item / (npairs * 32);
    const int k0 = s * 16 + tg * 2;

    uint32_t h[4], l[4];
#pragma unroll
    for (int half = 0; half < 2; ++half) {
        const int n = (jp * 2 + half) * 8 + gid;
        const float f00 = W[(size_t)k0 * ldW + n];
        const float f01 = W[(size_t)(k0 + 1) * ldW + n];
        const float f10 = W[(size_t)(k0 + 8) * ldW + n];
        const float f11 = W[(size_t)(k0 + 9) * ldW + n];
        float r00, r01, r10, r11, d0, d1;
        if (f16) {
            h[half * 2 + 0] = pack_h_pair(f00, f01, r00, r01);
            h[half * 2 + 1] = pack_h_pair(f10, f11, r10, r11);
            l[half * 2 + 0] = pack_h_pair(r00, r01, d0, d1);
            l[half * 2 + 1] = pack_h_pair(r10, r11, d0, d1);
        } else {
            h[half * 2 + 0] = pack_bf_pair(f00, f01, r00, r01);
            h[half * 2 + 1] = pack_bf_pair(f10, f11, r10, r11);
            l[half * 2 + 0] = pack_bf_pair(r00, r01, d0, d1);
            l[half * 2 + 1] = pack_bf_pair(r10, r11, d0, d1);
        }
    }
    const int dst = (s * npairs + jp) * 32 + lane;
    dH[dst] = make_uint4(h[0], h[1], h[2], h[3]);
    dL[dst] = make_uint4(l[0], l[1], l[2], l[3]);
}

__global__ void mega_pack_kernel(const float* __restrict__ eW1, const float* __restrict__ eW2,
                                 const float* __restrict__ nW1, const float* __restrict__ nW2,
                                 const float* __restrict__ nW3,
                                 const float* __restrict__ eb3, const float* __restrict__ nb1)
{
    const int idx = blockIdx.x * 256 + threadIdx.x;
    if (idx < 8192)        pack_item(eW1,             512, 32, g_eW1aH, g_eW1aL, true,  idx);
    else if (idx < 16384)  pack_item(eW1 + 128 * 512, 512, 32, g_eW1bH, g_eW1bL, true,  idx - 8192);
    else if (idx < 49152)  pack_item(eW2,             512, 32, g_W2H,   g_W2L,   true,  idx - 16384);
    else if (idx < 57344)  pack_item(nW1,             512, 32, g_nW1aH, g_nW1aL, true,  idx - 49152);
    else if (idx < 90112)  pack_item(nW1 + 132 * 512, 512, 32, g_nW1cH, g_nW1cL, false, idx - 57344);
    else if (idx < 122880) pack_item(nW2,             512, 32, g_nW2H,  g_nW2L,  true,  idx - 90112);
    else if (idx < 131072) pack_item(nW3,             128, 8,  g_nW3H,  g_nW3L,  true,  idx - 122880);
    else if (idx < 131584) {
        const int n = idx - 131072;
        float acc = 0.f;
#pragma unroll 8
        for (int k = 0; k < 512; ++k)
            acc += eb3[k] * nW1[(size_t)(132 + k) * 512 + n];
        g_bp[n] = nb1[n] + 15.f * acc;
    }
}

__global__ void pack_frag_kernel(const float* __restrict__ W, int npairs,
                                 uint4* __restrict__ dstH, uint4* __restrict__ dstL, int f16)
{
    const int idx = blockIdx.x * 256 + threadIdx.x;
    pack_item(W, npairs * 16, npairs, dstH, dstL, f16 != 0, idx);
}

// ================= Wcomb GEMM (bf16 3-term, 2-stage) =================
__global__ void __launch_bounds__(256, 1) wc_gemm_kernel(
    const float* __restrict__ X,
    const uint4* __restrict__ WH, const uint4* __restrict__ WL,
    float* __restrict__ out)
{
    extern __shared__ __align__(16) char smem[];
    const uint32_t sbase = smem_u32(smem);
    const int tid = threadIdx.x;
    const int bm = blockIdx.x * 64;
    const int A_ST = 1040;
    const uint32_t offALO = 64 * 1040;
    const uint32_t offB = 2 * offALO;

    for (int idx = tid; idx < 64 * 128; idx += 256) {
        const int m = idx >> 7, k4 = (idx & 127) << 2;
        const float4 v = *(const float4*)(X + (size_t)(bm + m) * 512 + k4);
        float rx, ry, rz, rw, d0, d1;
        uint2 hh, ll;
        hh.x = pack_bf_pair(v.x, v.y, rx, ry);
        hh.y = pack_bf_pair(v.z, v.w, rz, rw);
        ll.x = pack_bf_pair(rx, ry, d0, d1);
        ll.y = pack_bf_pair(rz, rw, d0, d1);
        const uint32_t off = (uint32_t)m * A_ST + ((uint32_t)k4 << 1);
        *(uint2*)(smem + off) = hh;
        *(uint2*)(smem + offALO + off) = ll;
    }
    __syncthreads();

    const int w = tid >> 5, lane = tid & 31;
    const int gid = lane >> 2, tg = lane & 3;
    const int lrow = (lane & 8) + (lane & 7);
    const uint32_t a_base = sbase + (uint32_t)lrow * A_ST + ((lane & 16) ? 16u : 0u);

    float acc[4][8][4];
#pragma unroll
    for (int mt = 0; mt < 4; ++mt)
#pragma unroll
        for (int nt = 0; nt < 8; ++nt)
#pragma unroll
            for (int j = 0; j < 4; ++j) acc[mt][nt][j] = 0.f;

    auto stageB = [&](int stage, int s) {
#pragma unroll
        for (int p = 0; p < 4; ++p) {
            const int jpg = w * 4 + p;
            const uint32_t d = sbase + offB +
                ((uint32_t)((stage * 32 + jpg) * 2) * 32 + lane) * 16;
            CP_ASYNC16(d, WH + ((size_t)(s * 32 + jpg) * 32 + lane));
            CP_ASYNC16(d + 512, WL + ((size_t)(s * 32 + jpg) * 32 + lane));
        }
    };
    stageB(0, 0); CP_COMMIT();
    for (int s = 0; s < 32; ++s) {
        const int cur = s & 1;
        if (s < 31) { stageB(cur ^ 1, s + 1); CP_COMMIT(); CP_WAIT1(); }
        else CP_WAIT0();
        uint4 vh[4], vl[4];
#pragma unroll
        for (int p = 0; p < 4; ++p) {
            const uint32_t aH = sbase + offB +
                ((uint32_t)((cur * 32 + w * 4 + p) * 2) * 32 + lane) * 16;
            vh[p] = lds128(aH);
            vl[p] = lds128(aH + 512);
        }
        uint32_t ah[4][4], al[4][4];
#pragma unroll
        for (int mt = 0; mt < 4; ++mt) {
            const uint32_t aoff = (uint32_t)mt * 16 * A_ST + (uint32_t)s * 32;
            ldsm4(ah[mt], a_base + aoff);
            ldsm4(al[mt], a_base + offALO + aoff);
        }
#pragma unroll
        for (int mt = 0; mt < 4; ++mt)
#pragma unroll
            for (int p = 0; p < 4; ++p) {
                mma_bf16(acc[mt][2 * p],     ah[mt], vh[p].x, vh[p].y);
                mma_bf16(acc[mt][2 * p + 1], ah[mt], vh[p].z, vh[p].w);
                mma_bf16(acc[mt][2 * p],     ah[mt], vl[p].x, vl[p].y);
                mma_bf16(acc[mt][2 * p + 1], ah[mt], vl[p].z, vl[p].w);
                mma_bf16(acc[mt][2 * p],     al[mt], vh[p].x, vh[p].y);
                mma_bf16(acc[mt][2 * p + 1], al[mt], vh[p].z, vh[p].w);
            }
    }
    const int colb = w * 64 + tg * 2;
#pragma unroll
    for (int mt = 0; mt < 4; ++mt) {
        const int r0 = bm + mt * 16 + gid, r1 = r0 + 8;
#pragma unroll
        for (int nt = 0; nt < 8; ++nt) {
            const int col = colb + nt * 8;
            *(float2*)(out + (size_t)r0 * 512 + col) = make_float2(acc[mt][nt][0], acc[mt][nt][1]);
            *(float2*)(out + (size_t)r1 * 512 + col) = make_float2(acc[mt][nt][2], acc[mt][nt][3]);
        }
    }
}

// ================= P/Q/T kernel (K=128, fp16 2-term, phase-split grid.y) =================
#define PQT_A_ST 272
#define PQT_OFFB (64 * 272)
#define SMEM_PQT (PQT_OFFB + 4 * 32768)

__global__ void __launch_bounds__(256, 1) pqt_kernel(
    const float* __restrict__ X, const float* __restrict__ actW,
    const int* __restrict__ action)
{
    extern __shared__ __align__(16) char smem[];
    const uint32_t sbase = smem_u32(smem);
    const int tid = threadIdx.x;
    const int bm = blockIdx.x * 64;
    const int ph = blockIdx.y;                // 0 = P, 1 = Q, 2 = T
    const int w = tid >> 5, lane = tid & 31;
    const int gid = lane >> 2, tg = lane & 3;

    const uint4* WH = (ph == 0) ? g_eW1aH : (ph == 1) ? g_eW1bH : g_nW1aH;
    const uint4* WL = (ph == 0) ? g_eW1aL : (ph == 1) ? g_eW1bL : g_nW1aL;

    auto stageB = [&](int stage, int s) {
#pragma unroll
        for (int p = 0; p < 4; ++p) {
            const int jpg = w * 4 + p;
            const uint32_t d = sbase + PQT_OFFB +
                ((uint32_t)((stage * 32 + jpg) * 2) * 32 + lane) * 16;
            CP_ASYNC16(d, WH + ((size_t)(s * 32 + jpg) * 32 + lane));
            CP_ASYNC16(d + 512, WL + ((size_t)(s * 32 + jpg) * 32 + lane));
        }
    };

    stageB(0, 0); CP_COMMIT();
    stageB(1, 1); CP_COMMIT();
    stageB(2, 2); CP_COMMIT();

    // A = states (fp16 hi only)
    for (int idx = tid; idx < 64 * 32; idx += 256) {
        const int m = idx >> 5, k4 = (idx & 31) << 2;
        const float4 v = *(const float4*)(X + (size_t)(bm + m) * 128 + k4);
        float rx, ry, rz, rw;
        uint2 hh;
        hh.x = pack_h_pair(v.x, v.y, rx, ry);
        hh.y = pack_h_pair(v.z, v.w, rz, rw);
        *(uint2*)(smem + (uint32_t)m * PQT_A_ST + ((uint32_t)k4 << 1)) = hh;
    }
    __syncthreads();

    const int lrow = (lane & 8) + (lane & 7);
    const uint32_t a_base = sbase + (uint32_t)lrow * PQT_A_ST + ((lane & 16) ? 16u : 0u);
    const int colb = w * 64 + tg * 2;

    float acc[4][8][4];
#pragma unroll
    for (int mt = 0; mt < 4; ++mt)
#pragma unroll
        for (int nt = 0; nt < 8; ++nt)
#pragma unroll
            for (int j = 0; j < 4; ++j) acc[mt][nt][j] = 0.f;

    for (int s = 0; s < 8; ++s) {
        if (s + 3 < 8) { stageB((s + 3) & 3, s + 3); CP_COMMIT(); }
        const int rem = 7 - s;
        if (rem >= 3) CP_WAIT3(); else if (rem == 2) CP_WAIT2();
        else if (rem == 1) CP_WAIT1(); else CP_WAIT0();

        const int cur = s & 3;
        uint4 vh[4], vl[4];
#pragma unroll
        for (int p = 0; p < 4; ++p) {
            const uint32_t aH = sbase + PQT_OFFB +
                ((uint32_t)((cur * 32 + w * 4 + p) * 2) * 32 + lane) * 16;
            vh[p] = lds128(aH);
            vl[p] = lds128(aH + 512);
        }
        uint32_t ah[4][4];
#pragma unroll
        for (int mt = 0; mt < 4; ++mt)
            ldsm4(ah[mt], a_base + (uint32_t)mt * 16 * PQT_A_ST + (uint32_t)s * 32);
#pragma unroll
        for (int mt = 0; mt < 4; ++mt)
#pragma unroll
            for (int p = 0; p < 4; ++p) {
                mma_f16(acc[mt][2 * p],     ah[mt], vh[p].x, vh[p].y);
                mma_f16(acc[mt][2 * p + 1], ah[mt], vh[p].z, vh[p].w);
            }
#pragma unroll
        for (int mt = 0; mt < 4; ++mt)
#pragma unroll
            for (int p = 0; p < 4; ++p) {
                mma_f16(acc[mt][2 * p],     ah[mt], vl[p].x, vl[p].y);
                mma_f16(acc[mt][2 * p + 1], ah[mt], vl[p].z, vl[p].w);
            }
    }

#pragma unroll
    for (int mt = 0; mt < 4; ++mt) {
        const int r0 = bm + mt * 16 + gid, r1 = r0 + 8;
#pragma unroll
        for (int nt = 0; nt < 8; ++nt) {
            const int col = colb + nt * 8;
            float v00 = acc[mt][nt][0], v01 = acc[mt][nt][1];
            float v10 = acc[mt][nt][2], v11 = acc[mt][nt][3];
            if (ph == 2) {
                const float b0 = g_bp[col], b1 = g_bp[col + 1];
                v00 += b0; v01 += b1; v10 += b0; v11 += b1;
                const int a = action[r0 >> 4];
                const int t0 = a - 4 * (r0 & 15);
                const int t1 = a - 4 * (r1 & 15);
                if ((unsigned)t0 < 4u) {
                    v00 += __ldg(actW + (size_t)t0 * 512 + col);
                    v01 += __ldg(actW + (size_t)t0 * 512 + col + 1);
                }
                if ((unsigned)t1 < 4u) {
                    v10 += __ldg(actW + (size_t)t1 * 512 + col);
                    v11 += __ldg(actW + (size_t)t1 * 512 + col + 1);
                }
                *(float2*)&g_T[(size_t)r0 * 512 + col] = make_float2(v00, v01);
                *(float2*)&g_T[(size_t)r1 * 512 + col] = make_float2(v10, v11);
            } else {
                const int co = (ph == 1) ? 512 : 0;
                *(float2*)&g_PQ[(size_t)r0 * 1024 + co + col] = make_float2(v00, v01);
                *(float2*)&g_PQ[(size_t)r1 * 1024 + co + col] = make_float2(v10, v11);
            }
        }
    }
}

// ---------------- edge kernel: fp16 1-term, 256 threads, warp-private 4-stage ----------------
#define A_STRIDE 1040
#define OFF_BBUF  66560
#define OFF_B2    132096
#define OFF_GS    134144
#define OFF_BSS   136192
#define OFF_PS    138240
#define OFF_PQS   140288
#define OFF_MU    142336
#define OFF_RS    142592
#define SMEM_EDGE 142848

__device__ __forceinline__ void stage_B_edge(uint32_t sbase, int stage, int s, int w, int lane)
{
#pragma unroll
    for (int p = 0; p < 4; ++p) {
        const int jpg = w * 4 + p;
        const uint32_t dH = sbase + OFF_BBUF +
            ((uint32_t)(stage * 32 + jpg) * 32 + lane) * 16;
        CP_ASYNC16(dH, g_W2H + ((size_t)(s * 32 + jpg) * 32 + lane));
    }
}

__global__ void __launch_bounds__(256, 1) edge_mma_kernel(
    const float* __restrict__ eb1, const float* __restrict__ b2,
    const float* __restrict__ gam, const float* __restrict__ bet)
{
    extern __shared__ __align__(16) char smem[];
    const uint32_t sbase = smem_u32(smem);
    const int tid = threadIdx.x;
    const int nb = blockIdx.x;
    const int node_base = nb * 4;
    const int b16 = (nb >> 2) << 4;
    const int o0 = (nb & 3) * 4;
    const int w = tid >> 5, lane = tid & 31;

    float* b2s = (float*)(smem + OFF_B2);
    float* gss = (float*)(smem + OFF_GS);
    float* bss = (float*)(smem + OFF_BSS);
    float* ps  = (float*)(smem + OFF_PS);
    float* pq  = (float*)(smem + OFF_PQS);
    float* mus = (float*)(smem + OFF_MU);
    float* rss = (float*)(smem + OFF_RS);

    stage_B_edge(sbase, 0, 0, w, lane); CP_COMMIT();
    stage_B_edge(sbase, 1, 1, w, lane); CP_COMMIT();
    stage_B_edge(sbase, 2, 2, w, lane); CP_COMMIT();

    for (int i = tid; i < 512; i += 256) {
        b2s[i] = b2[i]; gss[i] = gam[i]; bss[i] = bet[i];
    }
    const float4* eb1v = (const float4*)eb1;
#pragma unroll
    for (int i = 0; i < 32; ++i) {
        const int idx = tid + (i << 8);
        const int m = idx >> 7;
        const int k4 = (idx & 127) << 2;
        const int ln = m >> 4, r = m & 15;
        float4 v = make_float4(0.f, 0.f, 0.f, 0.f);
        if (r < 15) {
            const int o = o0 + ln;
            const int jj = r + (r >= o);
            const float4 p4 = *(const float4*)&g_PQ[(size_t)(node_base + ln) * 1024 + k4];
            const float4 q4 = *(const float4*)&g_PQ[(size_t)(b16 + jj) * 1024 + 512 + k4];
            const float4 bb = __ldg(&eb1v[k4 >> 2]);
            v.x = fmaxf(p4.x + q4.x + bb.x, 0.f);
            v.y = fmaxf(p4.y + q4.y + bb.y, 0.f);
            v.z = fmaxf(p4.z + q4.z + bb.z, 0.f);
            v.w = fmaxf(p4.w + q4.w + bb.w, 0.f);
        }
        float rx, ry, rz, rw;
        uint2 hh;
        hh.x = pack_h_pair(v.x, v.y, rx, ry);
        hh.y = pack_h_pair(v.z, v.w, rz, rw);
        *(uint2*)(smem + (uint32_t)m * A_STRIDE + ((uint32_t)k4 << 1)) = hh;
    }
    __syncthreads();

    const int gid = lane >> 2, tg = lane & 3;
    const int lrow = (lane & 8) + (lane & 7);
    const uint32_t a_base = sbase + (uint32_t)lrow * A_STRIDE + ((lane & 16) ? 16u : 0u);

    float acc[4][8][4];
#pragma unroll
    for (int mt = 0; mt < 4; ++mt)
#pragma unroll
        for (int nt = 0; nt < 8; ++nt)
#pragma unroll
            for (int j = 0; j < 4; ++j) acc[mt][nt][j] = 0.f;

    for (int s = 0; s < 32; ++s) {
        if (s < 29) { stage_B_edge(sbase, (s + 3) & 3, s + 3, w, lane); CP_COMMIT(); CP_WAIT3(); }
        else if (s == 29) CP_WAIT2();
        else if (s == 30) CP_WAIT1();
        else CP_WAIT0();

        const int cur = s & 3;
        uint4 vh[4];
#pragma unroll
        for (int p = 0; p < 4; ++p) {
            const uint32_t aH = sbase + OFF_BBUF +
                ((uint32_t)(cur * 32 + w * 4 + p) * 32 + lane) * 16;
            vh[p] = lds128(aH);
        }
        uint32_t ah[4][4];
#pragma unroll
        for (int mt = 0; mt < 4; ++mt)
            ldsm4(ah[mt], a_base + (uint32_t)mt * (16 * A_STRIDE) + (uint32_t)s * 32);
#pragma unroll
        for (int mt = 0; mt < 4; ++mt)
#pragma unroll
            for (int p = 0; p < 4; ++p) {
                mma_f16(acc[mt][2 * p],     ah[mt], vh[p].x, vh[p].y);
                mma_f16(acc[mt][2 * p + 1], ah[mt], vh[p].z, vh[p].w);
            }
    }

    const int colb = w * 64 + tg * 2;
    float b2v[8][2];
#pragma unroll
    for (int nt = 0; nt < 8; ++nt) {
        b2v[nt][0] = b2s[colb + nt * 8];
        b2v[nt][1] = b2s[colb + nt * 8 + 1];
    }
#pragma unroll
    for (int mt = 0; mt < 4; ++mt) {
        float s0 = 0.f, q0 = 0.f, s1 = 0.f, q1 = 0.f;
#pragma unroll
        for (int nt = 0; nt < 8; ++nt) {
            const float v00 = acc[mt][nt][0] + b2v[nt][0];
            const float v01 = acc[mt][nt][1] + b2v[nt][1];
            const float v10 = acc[mt][nt][2] + b2v[nt][0];
            const float v11 = acc[mt][nt][3] + b2v[nt][1];
            acc[mt][nt][0] = v00; acc[mt][nt][1] = v01;
            acc[mt][nt][2] = v10; acc[mt][nt][3] = v11;
            s0 += v00 + v01; q0 += v00 * v00 + v01 * v01;
            s1 += v10 + v11; q1 += v10 * v10 + v11 * v11;
        }
#pragma unroll
        for (int off = 1; off <= 2; off <<= 1) {
            s0 += __shfl_xor_sync(0xffffffffu, s0, off);
            q0 += __shfl_xor_sync(0xffffffffu, q0, off);
            s1 += __shfl_xor_sync(0xffffffffu, s1, off);
            q1 += __shfl_xor_sync(0xffffffffu, q1, off);
        }
        if (tg == 0) {
            ps[(mt * 16 + gid) * 8 + w] = s0;     pq[(mt * 16 + gid) * 8 + w] = q0;
            ps[(mt * 16 + 8 + gid) * 8 + w] = s1; pq[(mt * 16 + 8 + gid) * 8 + w] = q1;
        }
    }
    __syncthreads();
    if (tid < 64) {
        float s = 0.f, q = 0.f;
#pragma unroll
        for (int ww = 0; ww < 8; ++ww) { s += ps[tid * 8 + ww]; q += pq[tid * 8 + ww]; }
        const float mu = s * (1.f / 512.f);
        mus[tid] = mu;
        rss[tid] = rsqrtf(q * (1.f / 512.f) - mu * mu + LN_EPS);
    }
    __syncthreads();

    float gv[8][2], bv[8][2];
#pragma unroll
    for (int nt = 0; nt < 8; ++nt) {
        gv[nt][0] = gss[colb + nt * 8];     gv[nt][1] = gss[colb + nt * 8 + 1];
        bv[nt][0] = bss[colb + nt * 8];     bv[nt][1] = bss[colb + nt * 8 + 1];
    }
#pragma unroll
    for (int mt = 0; mt < 4; ++mt) {
        const float mu0 = mus[mt * 16 + gid],     r0 = rss[mt * 16 + gid];
        const float mu1 = mus[mt * 16 + 8 + gid], r1 = rss[mt * 16 + 8 + gid];
        const bool last = (gid == 7);
#pragma unroll
        for (int nt = 0; nt < 8; ++nt) {
            const float v00 = fmaxf((acc[mt][nt][0] - mu0) * r0 * gv[nt][0] + bv[nt][0], 0.f);
            const float v01 = fmaxf((acc[mt][nt][1] - mu0) * r0 * gv[nt][1] + bv[nt][1], 0.f);
            const float v10 = last ? 0.f : fmaxf((acc[mt][nt][2] - mu1) * r1 * gv[nt][0] + bv[nt][0], 0.f);
            const float v11 = last ? 0.f : fmaxf((acc[mt][nt][3] - mu1) * r1 * gv[nt][1] + bv[nt][1], 0.f);
            float t0 = v00 + v10, t1 = v01 + v11;
#pragma unroll
            for (int off = 4; off <= 16; off <<= 1) {
                t0 += __shfl_xor_sync(0xffffffffu, t0, off);
                t1 += __shfl_xor_sync(0xffffffffu, t1, off);
            }
            if (lane < 4)
                *(float2*)&g_S[(size_t)(node_base + mt) * 512 + colb + nt * 8] =
                    make_float2(t0, t1);
        }
    }
}

// ---------------- fused tail: H1 -> H2 -> out ----------------
#define T_OFFB   66560
#define T_OFFPS  197632
#define T_OFFPQ  199680
#define T_OFFMU  201728
#define T_OFFRS  201984
#define SMEM_TAIL 202240

__global__ void __launch_bounds__(256, 1) tail_kernel(
    const float* __restrict__ Tm, const float* __restrict__ nb2,
    const float* __restrict__ gam, const float* __restrict__ bet,
    const float* __restrict__ nb3, float* __restrict__ out)
{
    extern __shared__ __align__(16) char smem[];
    const uint32_t sbase = smem_u32(smem);
    const int tid = threadIdx.x;
    const int bm = blockIdx.x * 64;
    const int w = tid >> 5, lane = tid & 31;
    const int gid = lane >> 2, tg = lane & 3;
    const int lrow = (lane & 8) + (lane & 7);
    const uint32_t a_base = sbase + (uint32_t)lrow * A_STRIDE + ((lane & 16) ? 16u : 0u);
    const int colb = w * 64 + tg * 2;
    float* ps  = (float*)(smem + T_OFFPS);
    float* pq  = (float*)(smem + T_OFFPQ);
    float* mus = (float*)(smem + T_OFFMU);
    float* rss = (float*)(smem + T_OFFRS);

    auto stage512 = [&](const uint4* WH, const uint4* WL, int stage, int s) {
#pragma unroll
        for (int p = 0; p < 4; ++p) {
            const int jpg = w * 4 + p;
            const uint32_t d = sbase + T_OFFB +
                ((uint32_t)((stage * 32 + jpg) * 2) * 32 + lane) * 16;
            CP_ASYNC16(d, WH + ((size_t)(s * 32 + jpg) * 32 + lane));
            CP_ASYNC16(d + 512, WL + ((size_t)(s * 32 + jpg) * 32 + lane));
        }
    };

    float acc[4][8][4];

    auto run512 = [&](const uint4* WH, const uint4* WL) {
#pragma unroll
        for (int mt = 0; mt < 4; ++mt)
#pragma unroll
            for (int nt = 0; nt < 8; ++nt)
#pragma unroll
                for (int j = 0; j < 4; ++j) acc[mt][nt][j] = 0.f;
        for (int s = 0; s < 32; ++s) {
            if (s < 29) { stage512(WH, WL, (s + 3) & 3, s + 3); CP_COMMIT(); CP_WAIT3(); }
            else if (s == 29) CP_WAIT2();
            else if (s == 30) CP_WAIT1();
            else CP_WAIT0();
            const int cur = s & 3;
            uint4 vh[4], vl[4];
#pragma unroll
            for (int p = 0; p < 4; ++p) {
                const uint32_t aH = sbase + T_OFFB +
                    ((uint32_t)((cur * 32 + w * 4 + p) * 2) * 32 + lane) * 16;
                vh[p] = lds128(aH);
                vl[p] = lds128(aH + 512);
            }
            uint32_t ah[4][4];
#pragma unroll
            for (int mt = 0; mt < 4; ++mt)
                ldsm4(ah[mt], a_base + (uint32_t)mt * (16 * A_STRIDE) + (uint32_t)s * 32);
#pragma unroll
            for (int mt = 0; mt < 4; ++mt)
#pragma unroll
                for (int p = 0; p < 4; ++p) {
                    mma_f16(acc[mt][2 * p],     ah[mt], vh[p].x, vh[p].y);
                    mma_f16(acc[mt][2 * p + 1], ah[mt], vh[p].z, vh[p].w);
                }
#pragma unroll
            for (int mt = 0; mt < 4; ++mt)
#pragma unroll
                for (int p = 0; p < 4; ++p) {
                    mma_f16(acc[mt][2 * p],     ah[mt], vl[p].x, vl[p].y);
                    mma_f16(acc[mt][2 * p + 1], ah[mt], vl[p].z, vl[p].w);
                }
        }
    };

    auto write_frags = [&]() {
        __syncthreads();
#pragma unroll
        for (int mt = 0; mt < 4; ++mt) {
            const int m0 = mt * 16 + gid, m1 = m0 + 8;
#pragma unroll
            for (int nt = 0; nt < 8; ++nt) {
                const int col = colb + nt * 8;
                float d0, d1;
                *(uint32_t*)(smem + (uint32_t)m0 * A_STRIDE + col * 2) =
                    pack_h_pair(acc[mt][nt][0], acc[mt][nt][1], d0, d1);
                *(uint32_t*)(smem + (uint32_t)m1 * A_STRIDE + col * 2) =
                    pack_h_pair(acc[mt][nt][2], acc[mt][nt][3], d0, d1);
            }
        }
        __syncthreads();
    };

    stage512(g_WcH, g_WcL, 0, 0); CP_COMMIT();
    stage512(g_WcH, g_WcL, 1, 1); CP_COMMIT();
    stage512(g_WcH, g_WcL, 2, 2); CP_COMMIT();

    for (int idx = tid; idx < 64 * 128; idx += 256) {
        const int m = idx >> 7, k4 = (idx & 127) << 2;
        const float4 v = *(const float4*)&g_S[(size_t)(bm + m) * 512 + k4];
        float rx, ry, rz, rw;
        uint2 hh;
        hh.x = pack_h_pair(v.x, v.y, rx, ry);
        hh.y = pack_h_pair(v.z, v.w, rz, rw);
        *(uint2*)(smem + (uint32_t)m * A_STRIDE + ((uint32_t)k4 << 1)) = hh;
    }
    __syncthreads();

    // loop1: H1 = relu(S@Wc + T)
    run512(g_WcH, g_WcL);
#pragma unroll
    for (int mt = 0; mt < 4; ++mt) {
        const int r0 = bm + mt * 16 + gid, r1 = r0 + 8;
#pragma unroll
        for (int nt = 0; nt < 8; ++nt) {
            const int col = colb + nt * 8;
            const float2 a0 = *(const float2*)(Tm + (size_t)r0 * 512 + col);
            const float2 a1 = *(const float2*)(Tm + (size_t)r1 * 512 + col);
            acc[mt][nt][0] = fmaxf(acc[mt][nt][0] + a0.x, 0.f);
            acc[mt][nt][1] = fmaxf(acc[mt][nt][1] + a0.y, 0.f);
            acc[mt][nt][2] = fmaxf(acc[mt][nt][2] + a1.x, 0.f);
            acc[mt][nt][3] = fmaxf(acc[mt][nt][3] + a1.y, 0.f);
        }
    }
    write_frags();

    // loop2: H2 = relu(LN(H1@nW2 + nb2))
    stage512(g_nW2H, g_nW2L, 0, 0); CP_COMMIT();
    stage512(g_nW2H, g_nW2L, 1, 1); CP_COMMIT();
    stage512(g_nW2H, g_nW2L, 2, 2); CP_COMMIT();
    run512(g_nW2H, g_nW2L);

#pragma unroll
    for (int mt = 0; mt < 4; ++mt) {
        float s0 = 0.f, q0 = 0.f, s1 = 0.f, q1 = 0.f;
#pragma unroll
        for (int nt = 0; nt < 8; ++nt) {
            const int col = colb + nt * 8;
            const float b0 = __ldg(nb2 + col), b1 = __ldg(nb2 + col + 1);
            const float v00 = acc[mt][nt][0] + b0;
            const float v01 = acc[mt][nt][1] + b1;
            const float v10 = acc[mt][nt][2] + b0;
            const float v11 = acc[mt][nt][3] + b1;
            acc[mt][nt][0] = v00; acc[mt][nt][1] = v01;
            acc[mt][nt][2] = v10; acc[mt][nt][3] = v11;
            s0 += v00 + v01; q0 += v00 * v00 + v01 * v01;
            s1 += v10 + v11; q1 += v10 * v10 + v11 * v11;
        }
#pragma unroll
        for (int off = 1; off <= 2; off <<= 1) {
            s0 += __shfl_xor_sync(0xffffffffu, s0, off);
            q0 += __shfl_xor_sync(0xffffffffu, q0, off);
            s1 += __shfl_xor_sync(0xffffffffu, s1, off);
            q1 += __shfl_xor_sync(0xffffffffu, q1, off);
        }
        if (tg == 0) {
            ps[(mt * 16 + gid) * 8 + w] = s0;     pq[(mt * 16 + gid) * 8 + w] = q0;
            ps[(mt * 16 + 8 + gid) * 8 + w] = s1; pq[(mt * 16 + 8 + gid) * 8 + w] = q1;
        }
    }
    __syncthreads();
    if (tid < 64) {
        float s = 0.f, q = 0.f;
#pragma unroll
        for (int ww = 0; ww < 8; ++ww) { s += ps[tid * 8 + ww]; q += pq[tid * 8 + ww]; }
        const float mu = s * (1.f / 512.f);
        mus[tid] = mu;
        rss[tid] = rsqrtf(q * (1.f / 512.f) - mu * mu + LN_EPS);
    }
    __syncthreads();
#pragma unroll
    for (int mt = 0; mt < 4; ++mt) {
        const float mu0 = mus[mt * 16 + gid],     rv0 = rss[mt * 16 + gid];
        const float mu1 = mus[mt * 16 + 8 + gid], rv1 = rss[mt * 16 + 8 + gid];
#pragma unroll
        for (int nt = 0; nt < 8; ++nt) {
            const int col = colb + nt * 8;
            const float g0 = __ldg(gam + col), g1 = __ldg(gam + col + 1);
            const float be0 = __ldg(bet + col), be1 = __ldg(bet + col + 1);
            acc[mt][nt][0] = fmaxf((acc[mt][nt][0] - mu0) * rv0 * g0 + be0, 0.f);
            acc[mt][nt][1] = fmaxf((acc[mt][nt][1] - mu0) * rv0 * g1 + be1, 0.f);
            acc[mt][nt][2] = fmaxf((acc[mt][nt][2] - mu1) * rv1 * g0 + be0, 0.f);
            acc[mt][nt][3] = fmaxf((acc[mt][nt][3] - mu1) * rv1 * g1 + be1, 0.f);
        }
    }
    write_frags();

    // loop3: out = H2@nW3 + nb3
    auto stage128 = [&](int stage, int s) {
        const uint32_t d = sbase + T_OFFB + (uint32_t)stage * 8192 +
            ((uint32_t)(w * 2) * 32 + lane) * 16;
        CP_ASYNC16(d, g_nW3H + ((size_t)(s * 8 + w) * 32 + lane));
        CP_ASYNC16(d + 512, g_nW3L + ((size_t)(s * 8 + w) * 32 + lane));
    };
    stage128(0, 0); CP_COMMIT();
    stage128(1, 1); CP_COMMIT();
    stage128(2, 2); CP_COMMIT();

    float acc3[4][2][4];
#pragma unroll
    for (int mt = 0; mt < 4; ++mt)
#pragma unroll
        for (int nt = 0; nt < 2; ++nt)
#pragma unroll
            for (int j = 0; j < 4; ++j) acc3[mt][nt][j] = 0.f;

    for (int s = 0; s < 32; ++s) {
        if (s < 29) { stage128((s + 3) & 3, s + 3); CP_COMMIT(); CP_WAIT3(); }
        else if (s == 29) CP_WAIT2();
        else if (s == 30) CP_WAIT1();
        else CP_WAIT0();
        const int cur = s & 3;
        const uint32_t aH = sbase + T_OFFB + (uint32_t)cur * 8192 +
            ((uint32_t)(w * 2) * 32 + lane) * 16;
        const uint4 vh = lds128(aH);
        const uint4 vl = lds128(aH + 512);
        uint32_t ah[4][4];
#pragma unroll
        for (int mt = 0; mt < 4; ++mt)
            ldsm4(ah[mt], a_base + (uint32_t)mt * (16 * A_STRIDE) + (uint32_t)s * 32);
#pragma unroll
        for (int mt = 0; mt < 4; ++mt) {
            mma_f16(acc3[mt][0], ah[mt], vh.x, vh.y);
            mma_f16(acc3[mt][1], ah[mt], vh.z, vh.w);
        }
#pragma unroll
        for (int mt = 0; mt < 4; ++mt) {
            mma_f16(acc3[mt][0], ah[mt], vl.x, vl.y);
            mma_f16(acc3[mt][1], ah[mt], vl.z, vl.w);
        }
    }
    const int colb3 = w * 16 + tg * 2;
#pragma unroll
    for (int mt = 0; mt < 4; ++mt) {
        const int r0 = bm + mt * 16 + gid, r1 = r0 + 8;
#pragma unroll
        for (int nt = 0; nt < 2; ++nt) {
            const int col = colb3 + nt * 8;
            const float b0 = __ldg(nb3 + col), b1 = __ldg(nb3 + col + 1);
            *(float2*)(out + (size_t)r0 * 128 + col) =
                make_float2(acc3[mt][nt][0] + b0, acc3[mt][nt][1] + b1);
            *(float2*)(out + (size_t)r1 * 128 + col) =
                make_float2(acc3[mt][nt][2] + b0, acc3[mt][nt][3] + b1);
        }
    }
}

// ---------------- launch ----------------
#define SMEM_WC (2 * 64 * 1040 + 2 * 32768 + 1024)

extern "C" void kernel_launch(void* const* d_in, const int* in_sizes, int n_in,
                              void* d_out, int out_size)
{
    const float* states = (const float*)d_in[0];
    const int*   action = (const int*)d_in[1];
    const float* eW1 = (const float*)d_in[2];
    const float* eb1 = (const float*)d_in[3];
    const float* eW2 = (const float*)d_in[4];
    const float* eb2 = (const float*)d_in[5];
    const float* eg  = (const float*)d_in[6];
    const float* ebt = (const float*)d_in[7];
    const float* eW3 = (const float*)d_in[8];
    const float* eb3 = (const float*)d_in[9];
    const float* nW1 = (const float*)d_in[10];
    const float* nb1 = (const float*)d_in[11];
    const float* nW2 = (const float*)d_in[12];
    const float* nb2 = (const float*)d_in[13];
    const float* ng  = (const float*)d_in[14];
    const float* nbt = (const float*)d_in[15];
    const float* nW3 = (const float*)d_in[16];
    const float* nb3 = (const float*)d_in[17];
    float* out = (float*)d_out;

    float *pT, *pH1;
    cudaGetSymbolAddress((void**)&pT,  g_T);
    cudaGetSymbolAddress((void**)&pH1, g_H1);

    uint4 *nW1cH, *nW1cL, *WcH, *WcL;
    cudaGetSymbolAddress((void**)&nW1cH, g_nW1cH);
    cudaGetSymbolAddress((void**)&nW1cL, g_nW1cL);
    cudaGetSymbolAddress((void**)&WcH, g_WcH);
    cudaGetSymbolAddress((void**)&WcL, g_WcL);

    static int configured = 0;
    if (!configured) {
        cudaFuncSetAttribute(edge_mma_kernel,
                             cudaFuncAttributeMaxDynamicSharedMemorySize, SMEM_EDGE);
        cudaFuncSetAttribute(pqt_kernel,
                             cudaFuncAttributeMaxDynamicSharedMemorySize, SMEM_PQT);
        cudaFuncSetAttribute(tail_kernel,
                             cudaFuncAttributeMaxDynamicSharedMemorySize, SMEM_TAIL);
        cudaFuncSetAttribute(wc_gemm_kernel,
                             cudaFuncAttributeMaxDynamicSharedMemorySize, SMEM_WC);
        configured = 1;
    }

    // 1) pack all weights + bprime
    mega_pack_kernel<<<514, 256>>>(eW1, eW2, nW1, nW2, nW3, eb3, nb1);
    // 2) Wcomb = eW3 @ nW1c (bf16 3-term), pack to fp16
    wc_gemm_kernel<<<8, 256, SMEM_WC>>>(eW3, nW1cH, nW1cL, pH1);
    pack_frag_kernel<<<128, 256>>>(pH1, 32, WcH, WcL, 1);
    // 3) P/Q/T phase-split: grid (128, 3), one phase per block
    pqt_kernel<<<dim3(NNODE / 64, 3), 256, SMEM_PQT>>>(states, nW1 + 128 * 512, action);
    // 4) fused edge layer (fp16 1-term) -> S
    edge_mma_kernel<<<NNODE / 4, 256, SMEM_EDGE>>>(eb1, eb2, eg, ebt);
    // 5) fused tail: H1 -> H2 -> out
    tail_kernel<<<NNODE / 64, 256, SMEM_TAIL>>>(pT, nb2, ng, nbt, nb3, out);
}

// round 15
// speedup vs baseline: 1.0182x; 1.0182x over previous
#include <cuda_runtime.h>
#include <cuda_bf16.h>
#include <cuda_fp16.h>
#include <math.h>
#include <stdint.h>

#define BB    512
#define OO    16
#define OBS   128
#define HH    512
#define NNODE (BB*OO)
#define LN_EPS 1e-5f

// ---------------- scratch ----------------
__device__ __align__(16) float g_PQ[(size_t)NNODE * 1024];
__device__ __align__(16) float g_S [(size_t)NNODE * HH];
__device__ __align__(16) float g_T [(size_t)NNODE * HH];
__device__ __align__(16) float g_H1[(size_t)NNODE * HH];   // Wcomb fp32 temp
__device__ __align__(16) float g_bp[512];

// fragment-packed weights
__device__ __align__(16) uint4 g_eW1aH[8192],  g_eW1aL[8192];    // fp16
__device__ __align__(16) uint4 g_eW1bH[8192],  g_eW1bL[8192];    // fp16
__device__ __align__(16) uint4 g_W2H[32768],   g_W2L[32768];     // fp16 (edge; lo unused)
__device__ __align__(16) uint4 g_nW1aH[8192],  g_nW1aL[8192];    // fp16
__device__ __align__(16) uint4 g_nW1cH[32768], g_nW1cL[32768];   // bf16 (for wc)
__device__ __align__(16) uint4 g_nW2H[32768],  g_nW2L[32768];    // fp16
__device__ __align__(16) uint4 g_nW3H[8192],   g_nW3L[8192];     // fp16
__device__ __align__(16) uint4 g_WcH[32768],   g_WcL[32768];     // fp16

// ---------------- helpers ----------------
__device__ __forceinline__ uint32_t smem_u32(const void* p) {
    uint32_t a;
    asm("{ .reg .u64 t; cvta.to.shared.u64 t, %1; cvt.u32.u64 %0, t; }" : "=r"(a) : "l"(p));
    return a;
}
__device__ __forceinline__ void ldsm4(uint32_t* r, uint32_t addr) {
    asm volatile("ldmatrix.sync.aligned.m8n8.x4.shared.b16 {%0,%1,%2,%3}, [%4];"
        : "=r"(r[0]), "=r"(r[1]), "=r"(r[2]), "=r"(r[3]) : "r"(addr));
}
__device__ __forceinline__ uint4 lds128(uint32_t a) {
    uint4 v;
    asm volatile("ld.shared.v4.b32 {%0,%1,%2,%3}, [%4];"
        : "=r"(v.x), "=r"(v.y), "=r"(v.z), "=r"(v.w) : "r"(a));
    return v;
}
__device__ __forceinline__ void mma_bf16(float* c, const uint32_t* a, uint32_t b0, uint32_t b1) {
    asm volatile(
        "mma.sync.aligned.m16n8k16.row.col.f32.bf16.bf16.f32 "
        "{%0,%1,%2,%3}, {%4,%5,%6,%7}, {%8,%9}, {%0,%1,%2,%3};"
        : "+f"(c[0]), "+f"(c[1]), "+f"(c[2]), "+f"(c[3])
        : "r"(a[0]), "r"(a[1]), "r"(a[2]), "r"(a[3]), "r"(b0), "r"(b1));
}
__device__ __forceinline__ void mma_f16(float* c, const uint32_t* a, uint32_t b0, uint32_t b1) {
    asm volatile(
        "mma.sync.aligned.m16n8k16.row.col.f32.f16.f16.f32 "
        "{%0,%1,%2,%3}, {%4,%5,%6,%7}, {%8,%9}, {%0,%1,%2,%3};"
        : "+f"(c[0]), "+f"(c[1]), "+f"(c[2]), "+f"(c[3])
        : "r"(a[0]), "r"(a[1]), "r"(a[2]), "r"(a[3]), "r"(b0), "r"(b1));
}
#define CP_ASYNC16(dst, src) \
    asm volatile("cp.async.cg.shared.global [%0], [%1], 16;" \
                 :: "r"(dst), "l"(__cvta_generic_to_global(src)))
#define CP_COMMIT() asm volatile("cp.async.commit_group;" ::: "memory")
#define CP_WAIT0()  asm volatile("cp.async.wait_group 0;" ::: "memory")
#define CP_WAIT1()  asm volatile("cp.async.wait_group 1;" ::: "memory")
#define CP_WAIT2()  asm volatile("cp.async.wait_group 2;" ::: "memory")
#define CP_WAIT3()  asm volatile("cp.async.wait_group 3;" ::: "memory")

__device__ __forceinline__ uint32_t pack_bf_pair(float a, float b, float& ra, float& rb) {
    const __nv_bfloat16 ha = __float2bfloat16(a), hb = __float2bfloat16(b);
    ra = a - __bfloat162float(ha);
    rb = b - __bfloat162float(hb);
    return (uint32_t)__bfloat16_as_ushort(ha) | ((uint32_t)__bfloat16_as_ushort(hb) << 16);
}
__device__ __forceinline__ uint32_t pack_h_pair(float a, float b, float& ra, float& rb) {
    const __half ha = __float2half_rn(a), hb = __float2half_rn(b);
    ra = a - __half2float(ha);
    rb = b - __half2float(hb);
    return (uint32_t)__half_as_ushort(ha) | ((uint32_t)__half_as_ushort(hb) << 16);
}

// ---------------- pack one fragment item ----------------
__device__ __forceinline__ void pack_item(
    const float* __restrict__ W, int ldW, int npairs,
    uint4* __restrict__ dH, uint4* __restrict__ dL, bool f16, int item)
{
    const int lane = item & 31;
    const int gid = lane >> 2, tg = lane & 3;
    const int jp = (item >> 5) % npairs;
    const int s = item / (npairs * 32);
    const int k0 = s * 16 + tg * 2;

    uint32_t h[4], l[4];
#pragma unroll
    for (int half = 0; half < 2; ++half) {
        const int n = (jp * 2 + half) * 8 + gid;
        const float f00 = W[(size_t)k0 * ldW + n];
        const float f01 = W[(size_t)(k0 + 1) * ldW + n];
        const float f10 = W[(size_t)(k0 + 8) * ldW + n];
        const float f11 = W[(size_t)(k0 + 9) * ldW + n];
        float r00, r01, r10, r11, d0, d1;
        if (f16) {
            h[half * 2 + 0] = pack_h_pair(f00, f01, r00, r01);
            h[half * 2 + 1] = pack_h_pair(f10, f11, r10, r11);
            l[half * 2 + 0] = pack_h_pair(r00, r01, d0, d1);
            l[half * 2 + 1] = pack_h_pair(r10, r11, d0, d1);
        } else {
            h[half * 2 + 0] = pack_bf_pair(f00, f01, r00, r01);
            h[half * 2 + 1] = pack_bf_pair(f10, f11, r10, r11);
            l[half * 2 + 0] = pack_bf_pair(r00, r01, d0, d1);
            l[half * 2 + 1] = pack_bf_pair(r10, r11, d0, d1);
        }
    }
    const int dst = (s * npairs + jp) * 32 + lane;
    dH[dst] = make_uint4(h[0], h[1], h[2], h[3]);
    dL[dst] = make_uint4(l[0], l[1], l[2], l[3]);
}

__global__ void mega_pack_kernel(const float* __restrict__ eW1, const float* __restrict__ eW2,
                                 const float* __restrict__ nW1, const float* __restrict__ nW2,
                                 const float* __restrict__ nW3,
                                 const float* __restrict__ eb3, const float* __restrict__ nb1)
{
    const int idx = blockIdx.x * 256 + threadIdx.x;
    if (idx < 8192)        pack_item(eW1,             512, 32, g_eW1aH, g_eW1aL, true,  idx);
    else if (idx < 16384)  pack_item(eW1 + 128 * 512, 512, 32, g_eW1bH, g_eW1bL, true,  idx - 8192);
    else if (idx < 49152)  pack_item(eW2,             512, 32, g_W2H,   g_W2L,   true,  idx - 16384);
    else if (idx < 57344)  pack_item(nW1,             512, 32, g_nW1aH, g_nW1aL, true,  idx - 49152);
    else if (idx < 90112)  pack_item(nW1 + 132 * 512, 512, 32, g_nW1cH, g_nW1cL, false, idx - 57344);
    else if (idx < 122880) pack_item(nW2,             512, 32, g_nW2H,  g_nW2L,  true,  idx - 90112);
    else if (idx < 131072) pack_item(nW3,             128, 8,  g_nW3H,  g_nW3L,  true,  idx - 122880);
    else if (idx < 131584) {
        const int n = idx - 131072;
        float acc = 0.f;
#pragma unroll 8
        for (int k = 0; k < 512; ++k)
            acc += eb3[k] * nW1[(size_t)(132 + k) * 512 + n];
        g_bp[n] = nb1[n] + 15.f * acc;
    }
}

__global__ void pack_frag_kernel(const float* __restrict__ W, int npairs,
                                 uint4* __restrict__ dstH, uint4* __restrict__ dstL, int f16)
{
    const int idx = blockIdx.x * 256 + threadIdx.x;
    pack_item(W, npairs * 16, npairs, dstH, dstL, f16 != 0, idx);
}

// ================= Wcomb GEMM (bf16 3-term, 2-stage) =================
__global__ void __launch_bounds__(256, 1) wc_gemm_kernel(
    const float* __restrict__ X,
    const uint4* __restrict__ WH, const uint4* __restrict__ WL,
    float* __restrict__ out)
{
    extern __shared__ __align__(16) char smem[];
    const uint32_t sbase = smem_u32(smem);
    const int tid = threadIdx.x;
    const int bm = blockIdx.x * 64;
    const int A_ST = 1040;
    const uint32_t offALO = 64 * 1040;
    const uint32_t offB = 2 * offALO;

    for (int idx = tid; idx < 64 * 128; idx += 256) {
        const int m = idx >> 7, k4 = (idx & 127) << 2;
        const float4 v = *(const float4*)(X + (size_t)(bm + m) * 512 + k4);
        float rx, ry, rz, rw, d0, d1;
        uint2 hh, ll;
        hh.x = pack_bf_pair(v.x, v.y, rx, ry);
        hh.y = pack_bf_pair(v.z, v.w, rz, rw);
        ll.x = pack_bf_pair(rx, ry, d0, d1);
        ll.y = pack_bf_pair(rz, rw, d0, d1);
        const uint32_t off = (uint32_t)m * A_ST + ((uint32_t)k4 << 1);
        *(uint2*)(smem + off) = hh;
        *(uint2*)(smem + offALO + off) = ll;
    }
    __syncthreads();

    const int w = tid >> 5, lane = tid & 31;
    const int gid = lane >> 2, tg = lane & 3;
    const int lrow = (lane & 8) + (lane & 7);
    const uint32_t a_base = sbase + (uint32_t)lrow * A_ST + ((lane & 16) ? 16u : 0u);

    float acc[4][8][4];
#pragma unroll
    for (int mt = 0; mt < 4; ++mt)
#pragma unroll
        for (int nt = 0; nt < 8; ++nt)
#pragma unroll
            for (int j = 0; j < 4; ++j) acc[mt][nt][j] = 0.f;

    auto stageB = [&](int stage, int s) {
#pragma unroll
        for (int p = 0; p < 4; ++p) {
            const int jpg = w * 4 + p;
            const uint32_t d = sbase + offB +
                ((uint32_t)((stage * 32 + jpg) * 2) * 32 + lane) * 16;
            CP_ASYNC16(d, WH + ((size_t)(s * 32 + jpg) * 32 + lane));
            CP_ASYNC16(d + 512, WL + ((size_t)(s * 32 + jpg) * 32 + lane));
        }
    };
    stageB(0, 0); CP_COMMIT();
    for (int s = 0; s < 32; ++s) {
        const int cur = s & 1;
        if (s < 31) { stageB(cur ^ 1, s + 1); CP_COMMIT(); CP_WAIT1(); }
        else CP_WAIT0();
        uint4 vh[4], vl[4];
#pragma unroll
        for (int p = 0; p < 4; ++p) {
            const uint32_t aH = sbase + offB +
                ((uint32_t)((cur * 32 + w * 4 + p) * 2) * 32 + lane) * 16;
            vh[p] = lds128(aH);
            vl[p] = lds128(aH + 512);
        }
        uint32_t ah[4][4], al[4][4];
#pragma unroll
        for (int mt = 0; mt < 4; ++mt) {
            const uint32_t aoff = (uint32_t)mt * 16 * A_ST + (uint32_t)s * 32;
            ldsm4(ah[mt], a_base + aoff);
            ldsm4(al[mt], a_base + offALO + aoff);
        }
#pragma unroll
        for (int mt = 0; mt < 4; ++mt)
#pragma unroll
            for (int p = 0; p < 4; ++p) {
                mma_bf16(acc[mt][2 * p],     ah[mt], vh[p].x, vh[p].y);
                mma_bf16(acc[mt][2 * p + 1], ah[mt], vh[p].z, vh[p].w);
                mma_bf16(acc[mt][2 * p],     ah[mt], vl[p].x, vl[p].y);
                mma_bf16(acc[mt][2 * p + 1], ah[mt], vl[p].z, vl[p].w);
                mma_bf16(acc[mt][2 * p],     al[mt], vh[p].x, vh[p].y);
                mma_bf16(acc[mt][2 * p + 1], al[mt], vh[p].z, vh[p].w);
            }
    }
    const int colb = w * 64 + tg * 2;
#pragma unroll
    for (int mt = 0; mt < 4; ++mt) {
        const int r0 = bm + mt * 16 + gid, r1 = r0 + 8;
#pragma unroll
        for (int nt = 0; nt < 8; ++nt) {
            const int col = colb + nt * 8;
            *(float2*)(out + (size_t)r0 * 512 + col) = make_float2(acc[mt][nt][0], acc[mt][nt][1]);
            *(float2*)(out + (size_t)r1 * 512 + col) = make_float2(acc[mt][nt][2], acc[mt][nt][3]);
        }
    }
}

// ================= fused P/Q/T kernel (K=128, fp16 2-term, continuous 24-step staging) =================
#define PQT_A_ST 272
#define PQT_OFFB (64 * 272)
#define SMEM_PQT (PQT_OFFB + 4 * 32768)

__global__ void __launch_bounds__(256, 1) pqt_kernel(
    const float* __restrict__ X, const float* __restrict__ actW,
    const int* __restrict__ action)
{
    extern __shared__ __align__(16) char smem[];
    const uint32_t sbase = smem_u32(smem);
    const int tid = threadIdx.x;
    const int bm = blockIdx.x * 64;
    const int w = tid >> 5, lane = tid & 31;
    const int gid = lane >> 2, tg = lane & 3;

    // continuous staging over 24 global steps; phase = gs>>3
    auto stageG = [&](int gs) {
        const int p3 = gs >> 3, sl = gs & 7;
        const uint4* WH = (p3 == 0) ? g_eW1aH : (p3 == 1) ? g_eW1bH : g_nW1aH;
        const uint4* WL = (p3 == 0) ? g_eW1aL : (p3 == 1) ? g_eW1bL : g_nW1aL;
        const int stage = gs & 3;
#pragma unroll
        for (int p = 0; p < 4; ++p) {
            const int jpg = w * 4 + p;
            const uint32_t d = sbase + PQT_OFFB +
                ((uint32_t)((stage * 32 + jpg) * 2) * 32 + lane) * 16;
            CP_ASYNC16(d, WH + ((size_t)(sl * 32 + jpg) * 32 + lane));
            CP_ASYNC16(d + 512, WL + ((size_t)(sl * 32 + jpg) * 32 + lane));
        }
    };

    stageG(0); CP_COMMIT();
    stageG(1); CP_COMMIT();
    stageG(2); CP_COMMIT();

    // A = states (fp16 hi only)
    for (int idx = tid; idx < 64 * 32; idx += 256) {
        const int m = idx >> 5, k4 = (idx & 31) << 2;
        const float4 v = *(const float4*)(X + (size_t)(bm + m) * 128 + k4);
        float rx, ry, rz, rw;
        uint2 hh;
        hh.x = pack_h_pair(v.x, v.y, rx, ry);
        hh.y = pack_h_pair(v.z, v.w, rz, rw);
        *(uint2*)(smem + (uint32_t)m * PQT_A_ST + ((uint32_t)k4 << 1)) = hh;
    }
    __syncthreads();

    const int lrow = (lane & 8) + (lane & 7);
    const uint32_t a_base = sbase + (uint32_t)lrow * PQT_A_ST + ((lane & 16) ? 16u : 0u);
    const int colb = w * 64 + tg * 2;

    float acc[4][8][4];
#pragma unroll
    for (int mt = 0; mt < 4; ++mt)
#pragma unroll
        for (int nt = 0; nt < 8; ++nt)
#pragma unroll
            for (int j = 0; j < 4; ++j) acc[mt][nt][j] = 0.f;

    for (int gs = 0; gs < 24; ++gs) {
        if (gs < 21) { stageG(gs + 3); CP_COMMIT(); CP_WAIT3(); }
        else if (gs == 21) CP_WAIT2();
        else if (gs == 22) CP_WAIT1();
        else CP_WAIT0();

        const int cur = gs & 3;
        const int sl = gs & 7;
        uint4 vh[4], vl[4];
#pragma unroll
        for (int p = 0; p < 4; ++p) {
            const uint32_t aH = sbase + PQT_OFFB +
                ((uint32_t)((cur * 32 + w * 4 + p) * 2) * 32 + lane) * 16;
            vh[p] = lds128(aH);
            vl[p] = lds128(aH + 512);
        }
        uint32_t ah[4][4];
#pragma unroll
        for (int mt = 0; mt < 4; ++mt)
            ldsm4(ah[mt], a_base + (uint32_t)mt * 16 * PQT_A_ST + (uint32_t)sl * 32);
#pragma unroll
        for (int mt = 0; mt < 4; ++mt)
#pragma unroll
            for (int p = 0; p < 4; ++p) {
                mma_f16(acc[mt][2 * p],     ah[mt], vh[p].x, vh[p].y);
                mma_f16(acc[mt][2 * p + 1], ah[mt], vh[p].z, vh[p].w);
            }
#pragma unroll
        for (int mt = 0; mt < 4; ++mt)
#pragma unroll
            for (int p = 0; p < 4; ++p) {
                mma_f16(acc[mt][2 * p],     ah[mt], vl[p].x, vl[p].y);
                mma_f16(acc[mt][2 * p + 1], ah[mt], vl[p].z, vl[p].w);
            }

        if ((gs & 7) == 7) {
            const int ph = gs >> 3;
            // phase epilogue (registers + gmem only; staging stays in flight)
#pragma unroll
            for (int mt = 0; mt < 4; ++mt) {
                const int r0 = bm + mt * 16 + gid, r1 = r0 + 8;
#pragma unroll
                for (int nt = 0; nt < 8; ++nt) {
                    const int col = colb + nt * 8;
                    float v00 = acc[mt][nt][0], v01 = acc[mt][nt][1];
                    float v10 = acc[mt][nt][2], v11 = acc[mt][nt][3];
                    if (ph == 2) {
                        const float b0 = g_bp[col], b1 = g_bp[col + 1];
                        v00 += b0; v01 += b1; v10 += b0; v11 += b1;
                        const int a = action[r0 >> 4];
                        const int t0 = a - 4 * (r0 & 15);
                        const int t1 = a - 4 * (r1 & 15);
                        if ((unsigned)t0 < 4u) {
                            v00 += __ldg(actW + (size_t)t0 * 512 + col);
                            v01 += __ldg(actW + (size_t)t0 * 512 + col + 1);
                        }
                        if ((unsigned)t1 < 4u) {
                            v10 += __ldg(actW + (size_t)t1 * 512 + col);
                            v11 += __ldg(actW + (size_t)t1 * 512 + col + 1);
                        }
                        *(float2*)&g_T[(size_t)r0 * 512 + col] = make_float2(v00, v01);
                        *(float2*)&g_T[(size_t)r1 * 512 + col] = make_float2(v10, v11);
                    } else {
                        const int co = (ph == 1) ? 512 : 0;
                        *(float2*)&g_PQ[(size_t)r0 * 1024 + co + col] = make_float2(v00, v01);
                        *(float2*)&g_PQ[(size_t)r1 * 1024 + co + col] = make_float2(v10, v11);
                    }
                    acc[mt][nt][0] = 0.f; acc[mt][nt][1] = 0.f;
                    acc[mt][nt][2] = 0.f; acc[mt][nt][3] = 0.f;
                }
            }
        }
    }
}

// ---------------- edge kernel: fp16 1-term, 256 threads, warp-private 4-stage ----------------
#define A_STRIDE 1040
#define OFF_BBUF  66560
#define OFF_B2    132096
#define OFF_GS    134144
#define OFF_BSS   136192
#define OFF_PS    138240
#define OFF_PQS   140288
#define OFF_MU    142336
#define OFF_RS    142592
#define SMEM_EDGE 142848

__device__ __forceinline__ void stage_B_edge(uint32_t sbase, int stage, int s, int w, int lane)
{
#pragma unroll
    for (int p = 0; p < 4; ++p) {
        const int jpg = w * 4 + p;
        const uint32_t dH = sbase + OFF_BBUF +
            ((uint32_t)(stage * 32 + jpg) * 32 + lane) * 16;
        CP_ASYNC16(dH, g_W2H + ((size_t)(s * 32 + jpg) * 32 + lane));
    }
}

__global__ void __launch_bounds__(256, 1) edge_mma_kernel(
    const float* __restrict__ eb1, const float* __restrict__ b2,
    const float* __restrict__ gam, const float* __restrict__ bet)
{
    extern __shared__ __align__(16) char smem[];
    const uint32_t sbase = smem_u32(smem);
    const int tid = threadIdx.x;
    const int nb = blockIdx.x;
    const int node_base = nb * 4;
    const int b16 = (nb >> 2) << 4;
    const int o0 = (nb & 3) * 4;
    const int w = tid >> 5, lane = tid & 31;

    float* b2s = (float*)(smem + OFF_B2);
    float* gss = (float*)(smem + OFF_GS);
    float* bss = (float*)(smem + OFF_BSS);
    float* ps  = (float*)(smem + OFF_PS);
    float* pq  = (float*)(smem + OFF_PQS);
    float* mus = (float*)(smem + OFF_MU);
    float* rss = (float*)(smem + OFF_RS);

    stage_B_edge(sbase, 0, 0, w, lane); CP_COMMIT();
    stage_B_edge(sbase, 1, 1, w, lane); CP_COMMIT();
    stage_B_edge(sbase, 2, 2, w, lane); CP_COMMIT();

    for (int i = tid; i < 512; i += 256) {
        b2s[i] = b2[i]; gss[i] = gam[i]; bss[i] = bet[i];
    }
    const float4* eb1v = (const float4*)eb1;
#pragma unroll
    for (int i = 0; i < 32; ++i) {
        const int idx = tid + (i << 8);
        const int m = idx >> 7;
        const int k4 = (idx & 127) << 2;
        const int ln = m >> 4, r = m & 15;
        float4 v = make_float4(0.f, 0.f, 0.f, 0.f);
        if (r < 15) {
            const int o = o0 + ln;
            const int jj = r + (r >= o);
            const float4 p4 = *(const float4*)&g_PQ[(size_t)(node_base + ln) * 1024 + k4];
            const float4 q4 = *(const float4*)&g_PQ[(size_t)(b16 + jj) * 1024 + 512 + k4];
            const float4 bb = __ldg(&eb1v[k4 >> 2]);
            v.x = fmaxf(p4.x + q4.x + bb.x, 0.f);
            v.y = fmaxf(p4.y + q4.y + bb.y, 0.f);
            v.z = fmaxf(p4.z + q4.z + bb.z, 0.f);
            v.w = fmaxf(p4.w + q4.w + bb.w, 0.f);
        }
        float rx, ry, rz, rw;
        uint2 hh;
        hh.x = pack_h_pair(v.x, v.y, rx, ry);
        hh.y = pack_h_pair(v.z, v.w, rz, rw);
        *(uint2*)(smem + (uint32_t)m * A_STRIDE + ((uint32_t)k4 << 1)) = hh;
    }
    __syncthreads();

    const int gid = lane >> 2, tg = lane & 3;
    const int lrow = (lane & 8) + (lane & 7);
    const uint32_t a_base = sbase + (uint32_t)lrow * A_STRIDE + ((lane & 16) ? 16u : 0u);

    float acc[4][8][4];
#pragma unroll
    for (int mt = 0; mt < 4; ++mt)
#pragma unroll
        for (int nt = 0; nt < 8; ++nt)
#pragma unroll
            for (int j = 0; j < 4; ++j) acc[mt][nt][j] = 0.f;

    for (int s = 0; s < 32; ++s) {
        if (s < 29) { stage_B_edge(sbase, (s + 3) & 3, s + 3, w, lane); CP_COMMIT(); CP_WAIT3(); }
        else if (s == 29) CP_WAIT2();
        else if (s == 30) CP_WAIT1();
        else CP_WAIT0();

        const int cur = s & 3;
        uint4 vh[4];
#pragma unroll
        for (int p = 0; p < 4; ++p) {
            const uint32_t aH = sbase + OFF_BBUF +
                ((uint32_t)(cur * 32 + w * 4 + p) * 32 + lane) * 16;
            vh[p] = lds128(aH);
        }
        uint32_t ah[4][4];
#pragma unroll
        for (int mt = 0; mt < 4; ++mt)
            ldsm4(ah[mt], a_base + (uint32_t)mt * (16 * A_STRIDE) + (uint32_t)s * 32);
#pragma unroll
        for (int mt = 0; mt < 4; ++mt)
#pragma unroll
            for (int p = 0; p < 4; ++p) {
                mma_f16(acc[mt][2 * p],     ah[mt], vh[p].x, vh[p].y);
                mma_f16(acc[mt][2 * p + 1], ah[mt], vh[p].z, vh[p].w);
            }
    }

    const int colb = w * 64 + tg * 2;
    float b2v[8][2];
#pragma unroll
    for (int nt = 0; nt < 8; ++nt) {
        b2v[nt][0] = b2s[colb + nt * 8];
        b2v[nt][1] = b2s[colb + nt * 8 + 1];
    }
#pragma unroll
    for (int mt = 0; mt < 4; ++mt) {
        float s0 = 0.f, q0 = 0.f, s1 = 0.f, q1 = 0.f;
#pragma unroll
        for (int nt = 0; nt < 8; ++nt) {
            const float v00 = acc[mt][nt][0] + b2v[nt][0];
            const float v01 = acc[mt][nt][1] + b2v[nt][1];
            const float v10 = acc[mt][nt][2] + b2v[nt][0];
            const float v11 = acc[mt][nt][3] + b2v[nt][1];
            acc[mt][nt][0] = v00; acc[mt][nt][1] = v01;
            acc[mt][nt][2] = v10; acc[mt][nt][3] = v11;
            s0 += v00 + v01; q0 += v00 * v00 + v01 * v01;
            s1 += v10 + v11; q1 += v10 * v10 + v11 * v11;
        }
#pragma unroll
        for (int off = 1; off <= 2; off <<= 1) {
            s0 += __shfl_xor_sync(0xffffffffu, s0, off);
            q0 += __shfl_xor_sync(0xffffffffu, q0, off);
            s1 += __shfl_xor_sync(0xffffffffu, s1, off);
            q1 += __shfl_xor_sync(0xffffffffu, q1, off);
        }
        if (tg == 0) {
            ps[(mt * 16 + gid) * 8 + w] = s0;     pq[(mt * 16 + gid) * 8 + w] = q0;
            ps[(mt * 16 + 8 + gid) * 8 + w] = s1; pq[(mt * 16 + 8 + gid) * 8 + w] = q1;
        }
    }
    __syncthreads();
    if (tid < 64) {
        float s = 0.f, q = 0.f;
#pragma unroll
        for (int ww = 0; ww < 8; ++ww) { s += ps[tid * 8 + ww]; q += pq[tid * 8 + ww]; }
        const float mu = s * (1.f / 512.f);
        mus[tid] = mu;
        rss[tid] = rsqrtf(q * (1.f / 512.f) - mu * mu + LN_EPS);
    }
    __syncthreads();

    float gv[8][2], bv[8][2];
#pragma unroll
    for (int nt = 0; nt < 8; ++nt) {
        gv[nt][0] = gss[colb + nt * 8];     gv[nt][1] = gss[colb + nt * 8 + 1];
        bv[nt][0] = bss[colb + nt * 8];     bv[nt][1] = bss[colb + nt * 8 + 1];
    }
#pragma unroll
    for (int mt = 0; mt < 4; ++mt) {
        const float mu0 = mus[mt * 16 + gid],     r0 = rss[mt * 16 + gid];
        const float mu1 = mus[mt * 16 + 8 + gid], r1 = rss[mt * 16 + 8 + gid];
        const bool last = (gid == 7);
#pragma unroll
        for (int nt = 0; nt < 8; ++nt) {
            const float v00 = fmaxf((acc[mt][nt][0] - mu0) * r0 * gv[nt][0] + bv[nt][0], 0.f);
            const float v01 = fmaxf((acc[mt][nt][1] - mu0) * r0 * gv[nt][1] + bv[nt][1], 0.f);
            const float v10 = last ? 0.f : fmaxf((acc[mt][nt][2] - mu1) * r1 * gv[nt][0] + bv[nt][0], 0.f);
            const float v11 = last ? 0.f : fmaxf((acc[mt][nt][3] - mu1) * r1 * gv[nt][1] + bv[nt][1], 0.f);
            float t0 = v00 + v10, t1 = v01 + v11;
#pragma unroll
            for (int off = 4; off <= 16; off <<= 1) {
                t0 += __shfl_xor_sync(0xffffffffu, t0, off);
                t1 += __shfl_xor_sync(0xffffffffu, t1, off);
            }
            if (lane < 4)
                *(float2*)&g_S[(size_t)(node_base + mt) * 512 + colb + nt * 8] =
                    make_float2(t0, t1);
        }
    }
}

// ---------------- fused tail: H1 -> H2 -> out ----------------
#define T_OFFB   66560
#define T_OFFPS  197632
#define T_OFFPQ  199680
#define T_OFFMU  201728
#define T_OFFRS  201984
#define SMEM_TAIL 202240

__global__ void __launch_bounds__(256, 1) tail_kernel(
    const float* __restrict__ Tm, const float* __restrict__ nb2,
    const float* __restrict__ gam, const float* __restrict__ bet,
    const float* __restrict__ nb3, float* __restrict__ out)
{
    extern __shared__ __align__(16) char smem[];
    const uint32_t sbase = smem_u32(smem);
    const int tid = threadIdx.x;
    const int bm = blockIdx.x * 64;
    const int w = tid >> 5, lane = tid & 31;
    const int gid = lane >> 2, tg = lane & 3;
    const int lrow = (lane & 8) + (lane & 7);
    const uint32_t a_base = sbase + (uint32_t)lrow * A_STRIDE + ((lane & 16) ? 16u : 0u);
    const int colb = w * 64 + tg * 2;
    float* ps  = (float*)(smem + T_OFFPS);
    float* pq  = (float*)(smem + T_OFFPQ);
    float* mus = (float*)(smem + T_OFFMU);
    float* rss = (float*)(smem + T_OFFRS);

    auto stage512 = [&](const uint4* WH, const uint4* WL, int stage, int s) {
#pragma unroll
        for (int p = 0; p < 4; ++p) {
            const int jpg = w * 4 + p;
            const uint32_t d = sbase + T_OFFB +
                ((uint32_t)((stage * 32 + jpg) * 2) * 32 + lane) * 16;
            CP_ASYNC16(d, WH + ((size_t)(s * 32 + jpg) * 32 + lane));
            CP_ASYNC16(d + 512, WL + ((size_t)(s * 32 + jpg) * 32 + lane));
        }
    };

    float acc[4][8][4];

    auto run512 = [&](const uint4* WH, const uint4* WL) {
#pragma unroll
        for (int mt = 0; mt < 4; ++mt)
#pragma unroll
            for (int nt = 0; nt < 8; ++nt)
#pragma unroll
                for (int j = 0; j < 4; ++j) acc[mt][nt][j] = 0.f;
        for (int s = 0; s < 32; ++s) {
            if (s < 29) { stage512(WH, WL, (s + 3) & 3, s + 3); CP_COMMIT(); CP_WAIT3(); }
            else if (s == 29) CP_WAIT2();
            else if (s == 30) CP_WAIT1();
            else CP_WAIT0();
            const int cur = s & 3;
            uint4 vh[4], vl[4];
#pragma unroll
            for (int p = 0; p < 4; ++p) {
                const uint32_t aH = sbase + T_OFFB +
                    ((uint32_t)((cur * 32 + w * 4 + p) * 2) * 32 + lane) * 16;
                vh[p] = lds128(aH);
                vl[p] = lds128(aH + 512);
            }
            uint32_t ah[4][4];
#pragma unroll
            for (int mt = 0; mt < 4; ++mt)
                ldsm4(ah[mt], a_base + (uint32_t)mt * (16 * A_STRIDE) + (uint32_t)s * 32);
#pragma unroll
            for (int mt = 0; mt < 4; ++mt)
#pragma unroll
                for (int p = 0; p < 4; ++p) {
                    mma_f16(acc[mt][2 * p],     ah[mt], vh[p].x, vh[p].y);
                    mma_f16(acc[mt][2 * p + 1], ah[mt], vh[p].z, vh[p].w);
                }
#pragma unroll
            for (int mt = 0; mt < 4; ++mt)
#pragma unroll
                for (int p = 0; p < 4; ++p) {
                    mma_f16(acc[mt][2 * p],     ah[mt], vl[p].x, vl[p].y);
                    mma_f16(acc[mt][2 * p + 1], ah[mt], vl[p].z, vl[p].w);
                }
        }
    };

    auto write_frags = [&]() {
        __syncthreads();
#pragma unroll
        for (int mt = 0; mt < 4; ++mt) {
            const int m0 = mt * 16 + gid, m1 = m0 + 8;
#pragma unroll
            for (int nt = 0; nt < 8; ++nt) {
                const int col = colb + nt * 8;
                float d0, d1;
                *(uint32_t*)(smem + (uint32_t)m0 * A_STRIDE + col * 2) =
                    pack_h_pair(acc[mt][nt][0], acc[mt][nt][1], d0, d1);
                *(uint32_t*)(smem + (uint32_t)m1 * A_STRIDE + col * 2) =
                    pack_h_pair(acc[mt][nt][2], acc[mt][nt][3], d0, d1);
            }
        }
        __syncthreads();
    };

    stage512(g_WcH, g_WcL, 0, 0); CP_COMMIT();
    stage512(g_WcH, g_WcL, 1, 1); CP_COMMIT();
    stage512(g_WcH, g_WcL, 2, 2); CP_COMMIT();

    for (int idx = tid; idx < 64 * 128; idx += 256) {
        const int m = idx >> 7, k4 = (idx & 127) << 2;
        const float4 v = *(const float4*)&g_S[(size_t)(bm + m) * 512 + k4];
        float rx, ry, rz, rw;
        uint2 hh;
        hh.x = pack_h_pair(v.x, v.y, rx, ry);
        hh.y = pack_h_pair(v.z, v.w, rz, rw);
        *(uint2*)(smem + (uint32_t)m * A_STRIDE + ((uint32_t)k4 << 1)) = hh;
    }
    __syncthreads();

    // loop1: H1 = relu(S@Wc + T)
    run512(g_WcH, g_WcL);
#pragma unroll
    for (int mt = 0; mt < 4; ++mt) {
        const int r0 = bm + mt * 16 + gid, r1 = r0 + 8;
#pragma unroll
        for (int nt = 0; nt < 8; ++nt) {
            const int col = colb + nt * 8;
            const float2 a0 = *(const float2*)(Tm + (size_t)r0 * 512 + col);
            const float2 a1 = *(const float2*)(Tm + (size_t)r1 * 512 + col);
            acc[mt][nt][0] = fmaxf(acc[mt][nt][0] + a0.x, 0.f);
            acc[mt][nt][1] = fmaxf(acc[mt][nt][1] + a0.y, 0.f);
            acc[mt][nt][2] = fmaxf(acc[mt][nt][2] + a1.x, 0.f);
            acc[mt][nt][3] = fmaxf(acc[mt][nt][3] + a1.y, 0.f);
        }
    }
    write_frags();

    // loop2: H2 = relu(LN(H1@nW2 + nb2))
    stage512(g_nW2H, g_nW2L, 0, 0); CP_COMMIT();
    stage512(g_nW2H, g_nW2L, 1, 1); CP_COMMIT();
    stage512(g_nW2H, g_nW2L, 2, 2); CP_COMMIT();
    run512(g_nW2H, g_nW2L);

#pragma unroll
    for (int mt = 0; mt < 4; ++mt) {
        float s0 = 0.f, q0 = 0.f, s1 = 0.f, q1 = 0.f;
#pragma unroll
        for (int nt = 0; nt < 8; ++nt) {
            const int col = colb + nt * 8;
            const float b0 = __ldg(nb2 + col), b1 = __ldg(nb2 + col + 1);
            const float v00 = acc[mt][nt][0] + b0;
            const float v01 = acc[mt][nt][1] + b1;
            const float v10 = acc[mt][nt][2] + b0;
            const float v11 = acc[mt][nt][3] + b1;
            acc[mt][nt][0] = v00; acc[mt][nt][1] = v01;
            acc[mt][nt][2] = v10; acc[mt][nt][3] = v11;
            s0 += v00 + v01; q0 += v00 * v00 + v01 * v01;
            s1 += v10 + v11; q1 += v10 * v10 + v11 * v11;
        }
#pragma unroll
        for (int off = 1; off <= 2; off <<= 1) {
            s0 += __shfl_xor_sync(0xffffffffu, s0, off);
            q0 += __shfl_xor_sync(0xffffffffu, q0, off);
            s1 += __shfl_xor_sync(0xffffffffu, s1, off);
            q1 += __shfl_xor_sync(0xffffffffu, q1, off);
        }
        if (tg == 0) {
            ps[(mt * 16 + gid) * 8 + w] = s0;     pq[(mt * 16 + gid) * 8 + w] = q0;
            ps[(mt * 16 + 8 + gid) * 8 + w] = s1; pq[(mt * 16 + 8 + gid) * 8 + w] = q1;
        }
    }
    __syncthreads();
    if (tid < 64) {
        float s = 0.f, q = 0.f;
#pragma unroll
        for (int ww = 0; ww < 8; ++ww) { s += ps[tid * 8 + ww]; q += pq[tid * 8 + ww]; }
        const float mu = s * (1.f / 512.f);
        mus[tid] = mu;
        rss[tid] = rsqrtf(q * (1.f / 512.f) - mu * mu + LN_EPS);
    }
    __syncthreads();
#pragma unroll
    for (int mt = 0; mt < 4; ++mt) {
        const float mu0 = mus[mt * 16 + gid],     rv0 = rss[mt * 16 + gid];
        const float mu1 = mus[mt * 16 + 8 + gid], rv1 = rss[mt * 16 + 8 + gid];
#pragma unroll
        for (int nt = 0; nt < 8; ++nt) {
            const int col = colb + nt * 8;
            const float g0 = __ldg(gam + col), g1 = __ldg(gam + col + 1);
            const float be0 = __ldg(bet + col), be1 = __ldg(bet + col + 1);
            acc[mt][nt][0] = fmaxf((acc[mt][nt][0] - mu0) * rv0 * g0 + be0, 0.f);
            acc[mt][nt][1] = fmaxf((acc[mt][nt][1] - mu0) * rv0 * g1 + be1, 0.f);
            acc[mt][nt][2] = fmaxf((acc[mt][nt][2] - mu1) * rv1 * g0 + be0, 0.f);
            acc[mt][nt][3] = fmaxf((acc[mt][nt][3] - mu1) * rv1 * g1 + be1, 0.f);
        }
    }
    write_frags();

    // loop3: out = H2@nW3 + nb3
    auto stage128 = [&](int stage, int s) {
        const uint32_t d = sbase + T_OFFB + (uint32_t)stage * 8192 +
            ((uint32_t)(w * 2) * 32 + lane) * 16;
        CP_ASYNC16(d, g_nW3H + ((size_t)(s * 8 + w) * 32 + lane));
        CP_ASYNC16(d + 512, g_nW3L + ((size_t)(s * 8 + w) * 32 + lane));
    };
    stage128(0, 0); CP_COMMIT();
    stage128(1, 1); CP_COMMIT();
    stage128(2, 2); CP_COMMIT();

    float acc3[4][2][4];
#pragma unroll
    for (int mt = 0; mt < 4; ++mt)
#pragma unroll
        for (int nt = 0; nt < 2; ++nt)
#pragma unroll
            for (int j = 0; j < 4; ++j) acc3[mt][nt][j] = 0.f;

    for (int s = 0; s < 32; ++s) {
        if (s < 29) { stage128((s + 3) & 3, s + 3); CP_COMMIT(); CP_WAIT3(); }
        else if (s == 29) CP_WAIT2();
        else if (s == 30) CP_WAIT1();
        else CP_WAIT0();
        const int cur = s & 3;
        const uint32_t aH = sbase + T_OFFB + (uint32_t)cur * 8192 +
            ((uint32_t)(w * 2) * 32 + lane) * 16;
        const uint4 vh = lds128(aH);
        const uint4 vl = lds128(aH + 512);
        uint32_t ah[4][4];
#pragma unroll
        for (int mt = 0; mt < 4; ++mt)
            ldsm4(ah[mt], a_base + (uint32_t)mt * (16 * A_STRIDE) + (uint32_t)s * 32);
#pragma unroll
        for (int mt = 0; mt < 4; ++mt) {
            mma_f16(acc3[mt][0], ah[mt], vh.x, vh.y);
            mma_f16(acc3[mt][1], ah[mt], vh.z, vh.w);
        }
#pragma unroll
        for (int mt = 0; mt < 4; ++mt) {
            mma_f16(acc3[mt][0], ah[mt], vl.x, vl.y);
            mma_f16(acc3[mt][1], ah[mt], vl.z, vl.w);
        }
    }
    const int colb3 = w * 16 + tg * 2;
#pragma unroll
    for (int mt = 0; mt < 4; ++mt) {
        const int r0 = bm + mt * 16 + gid, r1 = r0 + 8;
#pragma unroll
        for (int nt = 0; nt < 2; ++nt) {
            const int col = colb3 + nt * 8;
            const float b0 = __ldg(nb3 + col), b1 = __ldg(nb3 + col + 1);
            *(float2*)(out + (size_t)r0 * 128 + col) =
                make_float2(acc3[mt][nt][0] + b0, acc3[mt][nt][1] + b1);
            *(float2*)(out + (size_t)r1 * 128 + col) =
                make_float2(acc3[mt][nt][2] + b0, acc3[mt][nt][3] + b1);
        }
    }
}

// ---------------- launch ----------------
#define SMEM_WC (2 * 64 * 1040 + 2 * 32768 + 1024)

extern "C" void kernel_launch(void* const* d_in, const int* in_sizes, int n_in,
                              void* d_out, int out_size)
{
    const float* states = (const float*)d_in[0];
    const int*   action = (const int*)d_in[1];
    const float* eW1 = (const float*)d_in[2];
    const float* eb1 = (const float*)d_in[3];
    const float* eW2 = (const float*)d_in[4];
    const float* eb2 = (const float*)d_in[5];
    const float* eg  = (const float*)d_in[6];
    const float* ebt = (const float*)d_in[7];
    const float* eW3 = (const float*)d_in[8];
    const float* eb3 = (const float*)d_in[9];
    const float* nW1 = (const float*)d_in[10];
    const float* nb1 = (const float*)d_in[11];
    const float* nW2 = (const float*)d_in[12];
    const float* nb2 = (const float*)d_in[13];
    const float* ng  = (const float*)d_in[14];
    const float* nbt = (const float*)d_in[15];
    const float* nW3 = (const float*)d_in[16];
    const float* nb3 = (const float*)d_in[17];
    float* out = (float*)d_out;

    float *pT, *pH1;
    cudaGetSymbolAddress((void**)&pT,  g_T);
    cudaGetSymbolAddress((void**)&pH1, g_H1);

    uint4 *nW1cH, *nW1cL, *WcH, *WcL;
    cudaGetSymbolAddress((void**)&nW1cH, g_nW1cH);
    cudaGetSymbolAddress((void**)&nW1cL, g_nW1cL);
    cudaGetSymbolAddress((void**)&WcH, g_WcH);
    cudaGetSymbolAddress((void**)&WcL, g_WcL);

    static int configured = 0;
    if (!configured) {
        cudaFuncSetAttribute(edge_mma_kernel,
                             cudaFuncAttributeMaxDynamicSharedMemorySize, SMEM_EDGE);
        cudaFuncSetAttribute(pqt_kernel,
                             cudaFuncAttributeMaxDynamicSharedMemorySize, SMEM_PQT);
        cudaFuncSetAttribute(tail_kernel,
                             cudaFuncAttributeMaxDynamicSharedMemorySize, SMEM_TAIL);
        cudaFuncSetAttribute(wc_gemm_kernel,
                             cudaFuncAttributeMaxDynamicSharedMemorySize, SMEM_WC);
        configured = 1;
    }

    // 1) pack all weights + bprime
    mega_pack_kernel<<<514, 256>>>(eW1, eW2, nW1, nW2, nW3, eb3, nb1);
    // 2) Wcomb = eW3 @ nW1c (bf16 3-term), pack to fp16
    wc_gemm_kernel<<<8, 256, SMEM_WC>>>(eW3, nW1cH, nW1cL, pH1);
    pack_frag_kernel<<<128, 256>>>(pH1, 32, WcH, WcL, 1);
    // 3) fused P/Q/T (fp16 2-term, continuous 24-step staging)
    pqt_kernel<<<NNODE / 64, 256, SMEM_PQT>>>(states, nW1 + 128 * 512, action);
    // 4) fused edge layer (fp16 1-term) -> S
    edge_mma_kernel<<<NNODE / 4, 256, SMEM_EDGE>>>(eb1, eb2, eg, ebt);
    // 5) fused tail: H1 -> H2 -> out
    tail_kernel<<<NNODE / 64, 256, SMEM_TAIL>>>(pT, nb2, ng, nbt, nb3, out);
}